// round 6
// baseline (speedup 1.0000x reference)
#include <cuda_runtime.h>

#define NVERTS 2000000
#define NFACES 4000000
#define NITERS 10
#define DT 1e-8f
#define BULK 2500.0f
#define M21 ((1ull<<21)-1ull)

// Scratch (device globals: allocation-free per harness rules)
__device__ float4 g_x[NVERTS];     // vertices (32 MB), updated only in vertex pass
__device__ float4 g_S[NVERTS];     // surface-tension accumulator (cross(h,d) sums)
__device__ float4 g_G[NVERTS];     // pressure-gradient accumulator (cross sums)
__device__ unsigned long long g_fp[NFACES];   // packed 3x21-bit indices (32 MB)
__device__ double g_vol;
__device__ float g_p;
__device__ unsigned int g_cnt;

__device__ __forceinline__ void red4(float4* p, float x, float y, float z) {
    asm volatile("red.global.add.v4.f32 [%0], {%1, %2, %3, %4};"
                 :: "l"(p), "f"(x), "f"(y), "f"(z), "f"(0.0f) : "memory");
}

// Block-level det reduction -> g_vol; the block performing the LAST counter
// increment of the launch finalizes exact p(x_t) for the SAME iteration's
// vertex pass (next launch). g_p is not read anywhere in this launch.
__device__ __forceinline__ void vol_reduce(float det) {
    #pragma unroll
    for (int o = 16; o > 0; o >>= 1) det += __shfl_down_sync(0xffffffffu, det, o);
    __shared__ float ws[8];
    if ((threadIdx.x & 31) == 0) ws[threadIdx.x >> 5] = det;
    __syncthreads();
    if (threadIdx.x == 0) {
        double s = 0.0;
        #pragma unroll
        for (int k = 0; k < 8; k++) s += (double)ws[k];
        atomicAdd(&g_vol, s);
        __threadfence();
        unsigned t = atomicInc(&g_cnt, gridDim.x - 1u);   // wraps to 0 on last
        if (t == gridDim.x - 1u) {
            double vol = g_vol * (1.0 / 6.0);
            float stv = expf(0.04f);                      // exp(PRESSURE0/BULK)
            g_p = BULK * (stv - (float)vol) / stv;
            g_vol = 0.0;
        }
    }
}

// ---------- prologue ----------

// Pack faces (auto int32/int64), seed x, zero accumulators.
__global__ void __launch_bounds__(256) k_init(const float* __restrict__ v,
                                              const void* __restrict__ fraw) {
    int i = blockIdx.x * 256 + threadIdx.x;

    const long long* f64 = (const long long*)fraw;
    const int* f32 = (const int*)fraw;
    bool is64 = true;
    #pragma unroll
    for (int k = 0; k < 8; k++)
        if ((unsigned long long)__ldg(&f64[k]) >= (unsigned long long)NVERTS) is64 = false;

    if (i < NFACES) {
        unsigned long long a, b, c;
        if (is64) {
            a = (unsigned long long)__ldg(&f64[3*i+0]);
            b = (unsigned long long)__ldg(&f64[3*i+1]);
            c = (unsigned long long)__ldg(&f64[3*i+2]);
        } else {
            a = (unsigned long long)(unsigned int)__ldg(&f32[3*i+0]);
            b = (unsigned long long)(unsigned int)__ldg(&f32[3*i+1]);
            c = (unsigned long long)(unsigned int)__ldg(&f32[3*i+2]);
        }
        g_fp[i] = a | (b << 21) | (c << 42);
    }
    if (i < NVERTS) {
        g_x[i] = make_float4(v[3*i], v[3*i+1], v[3*i+2], 0.0f);
        g_S[i] = make_float4(0.f, 0.f, 0.f, 0.f);
        g_G[i] = make_float4(0.f, 0.f, 0.f, 0.f);
    }
    if (i == 0) { g_vol = 0.0; g_cnt = 0u; }
}

// ---------- per-iteration ----------

// Pass A (faces): one gather of a,b,c; accumulate S (surface) and G
// (pressure gradient) via red.v4; reduce det -> exact p for this iteration.
__global__ void __launch_bounds__(256) k_face() {
    int i = blockIdx.x * 256 + threadIdx.x;            // exact cover of NFACES
    const float4* __restrict__ xs = g_x;

    unsigned long long f = __ldg(&g_fp[i]);
    int i0 = (int)(f & M21), i1 = (int)((f >> 21) & M21), i2 = (int)(f >> 42);
    float4 a = __ldg(&xs[i0]);
    float4 b = __ldg(&xs[i1]);
    float4 c = __ldg(&xs[i2]);

    // pressure-gradient parts: cross(b,c), cross(c,a), cross(a,b)
    float p0x = b.y*c.z - b.z*c.y, p0y = b.z*c.x - b.x*c.z, p0z = b.x*c.y - b.y*c.x;
    float p1x = c.y*a.z - c.z*a.y, p1y = c.z*a.x - c.x*a.z, p1z = c.x*a.y - c.y*a.x;
    float p2x = a.y*b.z - a.z*b.y, p2y = a.z*b.x - a.x*b.z, p2z = a.x*b.y - a.y*b.x;

    float det = a.x*p0x + a.y*p0y + a.z*p0z;           // 6*signed volume

    // unit normal
    float e1x = b.x - a.x, e1y = b.y - a.y, e1z = b.z - a.z;
    float e2x = c.x - a.x, e2y = c.y - a.y, e2z = c.z - a.z;
    float nx = e1y*e2z - e1z*e2y;
    float ny = e1z*e2x - e1x*e2z;
    float nz = e1x*e2y - e1y*e2x;
    float inv = 1.0f / (sqrtf(nx*nx + ny*ny + nz*nz) + 1e-12f);
    float hx = nx*inv, hy = ny*inv, hz = nz*inv;

    // surface parts (without the 0.5 factor): cross(h, v2-v1) etc.
    float d0x = c.x - b.x, d0y = c.y - b.y, d0z = c.z - b.z;
    float s0x = hy*d0z - hz*d0y, s0y = hz*d0x - hx*d0z, s0z = hx*d0y - hy*d0x;
    float d1x = a.x - c.x, d1y = a.y - c.y, d1z = a.z - c.z;
    float s1x = hy*d1z - hz*d1y, s1y = hz*d1x - hx*d1z, s1z = hx*d1y - hy*d1x;
    float s2x = hy*e1z - hz*e1y, s2y = hz*e1x - hx*e1z, s2z = hx*e1y - hy*e1x;

    red4(&g_S[i0], s0x, s0y, s0z);
    red4(&g_S[i1], s1x, s1y, s1z);
    red4(&g_S[i2], s2x, s2y, s2z);
    red4(&g_G[i0], p0x, p0y, p0z);
    red4(&g_G[i1], p1x, p1y, p1z);
    red4(&g_G[i2], p2x, p2y, p2z);

    vol_reduce(det);
}

// Pass B (vertices): x += dt*(-SURFACE_TENSION*0.5*S + (p/6)*G); zero S,G.
__global__ void __launch_bounds__(256) k_vert() {
    int i = blockIdx.x * 256 + threadIdx.x;
    if (i >= NVERTS) return;
    float4 s = g_S[i];
    float4 g = g_G[i];
    float4 x = g_x[i];
    float qs = -0.5f * DT;                 // dt * (-sigma) * 0.5
    float qp = g_p * (DT / 6.0f);          // dt * p / 6
    x.x += qs * s.x + qp * g.x;
    x.y += qs * s.y + qp * g.y;
    x.z += qs * s.z + qp * g.z;
    g_x[i] = x;
    g_S[i] = make_float4(0.f, 0.f, 0.f, 0.f);
    g_G[i] = make_float4(0.f, 0.f, 0.f, 0.f);
}

// Final: unpad into d_out.
__global__ void __launch_bounds__(256) k_pack(float* __restrict__ out) {
    int i = blockIdx.x * 256 + threadIdx.x;
    if (i < NVERTS) {
        float4 v = g_x[i];
        out[3*i] = v.x; out[3*i+1] = v.y; out[3*i+2] = v.z;
    }
}

extern "C" void kernel_launch(void* const* d_in, const int* in_sizes, int n_in,
                              void* d_out, int out_size) {
    const float* verts;
    const void* faces;
    if (in_sizes[0] == 3 * NVERTS) { verts = (const float*)d_in[0]; faces = d_in[1]; }
    else                           { verts = (const float*)d_in[1]; faces = d_in[0]; }

    const int FB = NFACES / 256;                    // 15625, exact cover
    const int VB = (NVERTS + 255) / 256;

    k_init<<<FB, 256>>>(verts, faces);
    for (int it = 0; it < NITERS; it++) {
        k_face<<<FB, 256>>>();                      // gather once + exact p
        k_vert<<<VB, 256>>>();                      // apply forces, zero accum
    }
    k_pack<<<VB, 256>>>((float*)d_out);
}

// round 7
// speedup vs baseline: 1.3294x; 1.3294x over previous
#include <cuda_runtime.h>

#define NVERTS 2000000
#define NFACES 4000000
#define NITERS 10
#define DT 1e-8f
#define BULK 2500.0f
#define M21 ((1ull<<21)-1ull)

// Scratch (device globals: allocation-free per harness rules)
__device__ float4 g_x[2][NVERTS];                 // double-buffered vertices (64 MB)
__device__ unsigned long long g_fp[NFACES];       // packed 3x21-bit indices (32 MB)
__device__ double g_vol;
__device__ float g_p;
__device__ unsigned int g_cnt;

__device__ __forceinline__ void red4(float4* p, float x, float y, float z) {
    asm volatile("red.global.add.v4.f32 [%0], {%1, %2, %3, %4};"
                 :: "l"(p), "f"(x), "f"(y), "f"(z), "f"(0.0f) : "memory");
}

// ---------- prologue ----------

// Pack faces (auto int32/int64), seed x[0], zero accumulators.
__global__ void __launch_bounds__(256) k_init(const float* __restrict__ v,
                                              const void* __restrict__ fraw) {
    int i = blockIdx.x * 256 + threadIdx.x;

    const long long* f64 = (const long long*)fraw;
    const int* f32 = (const int*)fraw;
    bool is64 = true;
    #pragma unroll
    for (int k = 0; k < 8; k++)
        if ((unsigned long long)__ldg(&f64[k]) >= (unsigned long long)NVERTS) is64 = false;

    if (i < NFACES) {
        unsigned long long a, b, c;
        if (is64) {
            a = (unsigned long long)__ldg(&f64[3*i+0]);
            b = (unsigned long long)__ldg(&f64[3*i+1]);
            c = (unsigned long long)__ldg(&f64[3*i+2]);
        } else {
            a = (unsigned long long)(unsigned int)__ldg(&f32[3*i+0]);
            b = (unsigned long long)(unsigned int)__ldg(&f32[3*i+1]);
            c = (unsigned long long)(unsigned int)__ldg(&f32[3*i+2]);
        }
        g_fp[i] = a | (b << 21) | (c << 42);
    }
    if (i < NVERTS) g_x[0][i] = make_float4(v[3*i], v[3*i+1], v[3*i+2], 0.0f);
    if (i == 0) { g_vol = 0.0; g_cnt = 0u; }
}

// ---------- per-iteration ----------

// Pass 1: copy x -> x' (1 vertex/thread, exact cover), volume reduction at
// 2 faces/thread for gather MLP; last block computes exact p(x_t).
__global__ void __launch_bounds__(256) k_vol(int src) {
    int i = blockIdx.x * 256 + threadIdx.x;           // pair index; grid covers NFACES/2
    const float4* __restrict__ xs = g_x[src];
    float4* __restrict__ xd = g_x[src ^ 1];
    if (i < NVERTS) xd[i] = __ldg(&xs[i]);            // fused double-buffer copy

    float det = 0.0f;
    if (i < NFACES/2) {
        ulonglong2 fp = __ldg((const ulonglong2*)g_fp + i);
        int a0 = (int)(fp.x & M21), a1 = (int)((fp.x >> 21) & M21), a2 = (int)(fp.x >> 42);
        int b0 = (int)(fp.y & M21), b1 = (int)((fp.y >> 21) & M21), b2 = (int)(fp.y >> 42);
        float4 A0 = __ldg(&xs[a0]); float4 B0 = __ldg(&xs[b0]);
        float4 A1 = __ldg(&xs[a1]); float4 B1 = __ldg(&xs[b1]);
        float4 A2 = __ldg(&xs[a2]); float4 B2 = __ldg(&xs[b2]);
        det  = A0.x * (A1.y * A2.z - A1.z * A2.y)
             + A0.y * (A1.z * A2.x - A1.x * A2.z)
             + A0.z * (A1.x * A2.y - A1.y * A2.x);
        det += B0.x * (B1.y * B2.z - B1.z * B2.y)
             + B0.y * (B1.z * B2.x - B1.x * B2.z)
             + B0.z * (B1.x * B2.y - B1.y * B2.x);
    }

    #pragma unroll
    for (int o = 16; o > 0; o >>= 1) det += __shfl_down_sync(0xffffffffu, det, o);
    __shared__ float ws[8];
    if ((threadIdx.x & 31) == 0) ws[threadIdx.x >> 5] = det;
    __syncthreads();
    if (threadIdx.x == 0) {
        double s = 0.0;
        #pragma unroll
        for (int k = 0; k < 8; k++) s += (double)ws[k];
        atomicAdd(&g_vol, s);
        __threadfence();
        unsigned t = atomicInc(&g_cnt, gridDim.x - 1u);   // wraps to 0 on last
        if (t == gridDim.x - 1u) {
            double vol = g_vol * (1.0 / 6.0);
            float stv = expf(0.04f);                      // exp(PRESSURE0/BULK)
            g_p = BULK * (stv - (float)vol) / stv;
            g_vol = 0.0;
        }
    }
}

// Pass 2: per-face forces with exact p, dt-scaled, scattered into x'.
__global__ void __launch_bounds__(256) k_force(int src) {
    int i = blockIdx.x * 256 + threadIdx.x;            // exact cover of NFACES
    const float4* __restrict__ xs = g_x[src];
    float4* xd = g_x[src ^ 1];

    unsigned long long f = __ldg(&g_fp[i]);
    int i0 = (int)(f & M21), i1 = (int)((f >> 21) & M21), i2 = (int)(f >> 42);
    float4 a = __ldg(&xs[i0]);
    float4 b = __ldg(&xs[i1]);
    float4 c = __ldg(&xs[i2]);

    float q = g_p * (DT / 6.0f);     // dt * p * (cross/6)
    const float s = 0.5f * DT;       // dt * SURFACE_TENSION * 0.5

    float e1x = b.x - a.x, e1y = b.y - a.y, e1z = b.z - a.z;
    float e2x = c.x - a.x, e2y = c.y - a.y, e2z = c.z - a.z;
    float nx = e1y * e2z - e1z * e2y;
    float ny = e1z * e2x - e1x * e2z;
    float nz = e1x * e2y - e1y * e2x;
    float inv = 1.0f / (sqrtf(nx*nx + ny*ny + nz*nz) + 1e-12f);
    float hx = nx * inv, hy = ny * inv, hz = nz * inv;

    float d0x = c.x - b.x, d0y = c.y - b.y, d0z = c.z - b.z;
    float g0x = q * (b.y*c.z - b.z*c.y) - s * (hy*d0z - hz*d0y);
    float g0y = q * (b.z*c.x - b.x*c.z) - s * (hz*d0x - hx*d0z);
    float g0z = q * (b.x*c.y - b.y*c.x) - s * (hx*d0y - hy*d0x);
    float d1x = a.x - c.x, d1y = a.y - c.y, d1z = a.z - c.z;
    float g1x = q * (c.y*a.z - c.z*a.y) - s * (hy*d1z - hz*d1y);
    float g1y = q * (c.z*a.x - c.x*a.z) - s * (hz*d1x - hx*d1z);
    float g1z = q * (c.x*a.y - c.y*a.x) - s * (hx*d1y - hy*d1x);
    float g2x = q * (a.y*b.z - a.z*b.y) - s * (hy*e1z - hz*e1y);
    float g2y = q * (a.z*b.x - a.x*b.z) - s * (hz*e1x - hx*e1z);
    float g2z = q * (a.x*b.y - a.y*b.x) - s * (hx*e1y - hy*e1x);

    red4(&xd[i0], g0x, g0y, g0z);
    red4(&xd[i1], g1x, g1y, g1z);
    red4(&xd[i2], g2x, g2y, g2z);
}

// Final: unpad into d_out.
__global__ void __launch_bounds__(256) k_pack(float* __restrict__ out, int src) {
    int i = blockIdx.x * 256 + threadIdx.x;
    if (i < NVERTS) {
        float4 v = g_x[src][i];
        out[3*i] = v.x; out[3*i+1] = v.y; out[3*i+2] = v.z;
    }
}

extern "C" void kernel_launch(void* const* d_in, const int* in_sizes, int n_in,
                              void* d_out, int out_size) {
    const float* verts;
    const void* faces;
    if (in_sizes[0] == 3 * NVERTS) { verts = (const float*)d_in[0]; faces = d_in[1]; }
    else                           { verts = (const float*)d_in[1]; faces = d_in[0]; }

    const int FB = NFACES / 256;                    // 15625, exact cover
    const int VB = (NFACES/2 + 255) / 256;          // 7813: covers pairs AND 2M verts
    const int CB = (NVERTS + 255) / 256;

    k_init<<<FB, 256>>>(verts, faces);
    int src = 0;
    for (int it = 0; it < NITERS; it++) {
        k_vol<<<VB, 256>>>(src);                    // copy + exact p(x_t)
        k_force<<<FB, 256>>>(src);                  // forces into x'
        src ^= 1;
    }
    k_pack<<<CB, 256>>>((float*)d_out, src);
}

// round 8
// speedup vs baseline: 1.3852x; 1.0420x over previous
#include <cuda_runtime.h>

#define NVERTS 2000000
#define NFACES 4000000
#define NITERS 10
#define DT 1e-8f
#define BULK 2500.0f
#define M21 ((1ull<<21)-1ull)

// Scratch (device globals: allocation-free per harness rules)
__device__ float4 g_x[2][NVERTS];                 // double-buffered vertices (64 MB)
__device__ unsigned long long g_fp[NFACES];       // packed 3x21-bit indices (32 MB)
__device__ double g_vol;
__device__ float g_p;
__device__ unsigned int g_cnt;

__device__ __forceinline__ void red4(float4* p, float x, float y, float z) {
    asm volatile("red.global.add.v4.f32 [%0], {%1, %2, %3, %4};"
                 :: "l"(p), "f"(x), "f"(y), "f"(z), "f"(0.0f) : "memory");
}

__device__ __forceinline__ float det3(float4 a, float4 b, float4 c) {
    return a.x * (b.y * c.z - b.z * c.y)
         + a.y * (b.z * c.x - b.x * c.z)
         + a.z * (b.x * c.y - b.y * c.x);
}

// ---------- prologue ----------

__global__ void __launch_bounds__(256) k_init(const float* __restrict__ v,
                                              const void* __restrict__ fraw) {
    int i = blockIdx.x * 256 + threadIdx.x;

    const long long* f64 = (const long long*)fraw;
    const int* f32 = (const int*)fraw;
    bool is64 = true;
    #pragma unroll
    for (int k = 0; k < 8; k++)
        if ((unsigned long long)__ldg(&f64[k]) >= (unsigned long long)NVERTS) is64 = false;

    if (i < NFACES) {
        unsigned long long a, b, c;
        if (is64) {
            a = (unsigned long long)__ldg(&f64[3*i+0]);
            b = (unsigned long long)__ldg(&f64[3*i+1]);
            c = (unsigned long long)__ldg(&f64[3*i+2]);
        } else {
            a = (unsigned long long)(unsigned int)__ldg(&f32[3*i+0]);
            b = (unsigned long long)(unsigned int)__ldg(&f32[3*i+1]);
            c = (unsigned long long)(unsigned int)__ldg(&f32[3*i+2]);
        }
        g_fp[i] = a | (b << 21) | (c << 42);
    }
    if (i < NVERTS) g_x[0][i] = make_float4(v[3*i], v[3*i+1], v[3*i+2], 0.0f);
    if (i == 0) { g_vol = 0.0; g_cnt = 0u; }
}

// ---------- per-iteration ----------

// Pass 1: copy x -> x' (2 verts/thread), det reduction at 4 faces/thread
// (12 outstanding gathers); last block computes exact p(x_t).
__global__ void __launch_bounds__(256) k_vol(int src) {
    int i = blockIdx.x * 256 + threadIdx.x;           // quad index
    const float4* __restrict__ xs = g_x[src];
    float4* __restrict__ xd = g_x[src ^ 1];
    if (2*i + 1 < NVERTS) {                           // fused copy, 2 verts/thread
        xd[2*i]     = __ldg(&xs[2*i]);
        xd[2*i + 1] = __ldg(&xs[2*i + 1]);
    }

    float det = 0.0f;
    if (i < NFACES/4) {
        ulonglong2 f01 = __ldg((const ulonglong2*)g_fp + 2*i);
        ulonglong2 f23 = __ldg((const ulonglong2*)g_fp + 2*i + 1);
        int a0=(int)(f01.x&M21), a1=(int)((f01.x>>21)&M21), a2=(int)(f01.x>>42);
        int b0=(int)(f01.y&M21), b1=(int)((f01.y>>21)&M21), b2=(int)(f01.y>>42);
        int c0=(int)(f23.x&M21), c1=(int)((f23.x>>21)&M21), c2=(int)(f23.x>>42);
        int d0=(int)(f23.y&M21), d1=(int)((f23.y>>21)&M21), d2=(int)(f23.y>>42);
        float4 A0=__ldg(&xs[a0]), A1=__ldg(&xs[a1]), A2=__ldg(&xs[a2]);
        float4 B0=__ldg(&xs[b0]), B1=__ldg(&xs[b1]), B2=__ldg(&xs[b2]);
        float4 C0=__ldg(&xs[c0]), C1=__ldg(&xs[c1]), C2=__ldg(&xs[c2]);
        float4 D0=__ldg(&xs[d0]), D1=__ldg(&xs[d1]), D2=__ldg(&xs[d2]);
        det = (det3(A0,A1,A2) + det3(B0,B1,B2))
            + (det3(C0,C1,C2) + det3(D0,D1,D2));
    }

    #pragma unroll
    for (int o = 16; o > 0; o >>= 1) det += __shfl_down_sync(0xffffffffu, det, o);
    __shared__ float ws[8];
    if ((threadIdx.x & 31) == 0) ws[threadIdx.x >> 5] = det;
    __syncthreads();
    if (threadIdx.x == 0) {
        double s = 0.0;
        #pragma unroll
        for (int k = 0; k < 8; k++) s += (double)ws[k];
        atomicAdd(&g_vol, s);
        __threadfence();
        unsigned t = atomicInc(&g_cnt, gridDim.x - 1u);   // wraps to 0 on last
        if (t == gridDim.x - 1u) {
            double vol = g_vol * (1.0 / 6.0);
            float stv = expf(0.04f);                      // exp(PRESSURE0/BULK)
            g_p = BULK * (stv - (float)vol) / stv;
            g_vol = 0.0;
        }
    }
}

// One face's force contribution, scattered dt-scaled into xd.
__device__ __forceinline__ void face_force(const float4* __restrict__ xs,
                                           float4* xd, unsigned long long f,
                                           float q, float s) {
    int i0 = (int)(f & M21), i1 = (int)((f >> 21) & M21), i2 = (int)(f >> 42);
    float4 a = __ldg(&xs[i0]);
    float4 b = __ldg(&xs[i1]);
    float4 c = __ldg(&xs[i2]);

    float e1x = b.x - a.x, e1y = b.y - a.y, e1z = b.z - a.z;
    float e2x = c.x - a.x, e2y = c.y - a.y, e2z = c.z - a.z;
    float nx = e1y * e2z - e1z * e2y;
    float ny = e1z * e2x - e1x * e2z;
    float nz = e1x * e2y - e1y * e2x;
    float inv = 1.0f / (sqrtf(nx*nx + ny*ny + nz*nz) + 1e-12f);
    float hx = nx * inv, hy = ny * inv, hz = nz * inv;

    float d0x = c.x - b.x, d0y = c.y - b.y, d0z = c.z - b.z;
    float g0x = q * (b.y*c.z - b.z*c.y) - s * (hy*d0z - hz*d0y);
    float g0y = q * (b.z*c.x - b.x*c.z) - s * (hz*d0x - hx*d0z);
    float g0z = q * (b.x*c.y - b.y*c.x) - s * (hx*d0y - hy*d0x);
    float d1x = a.x - c.x, d1y = a.y - c.y, d1z = a.z - c.z;
    float g1x = q * (c.y*a.z - c.z*a.y) - s * (hy*d1z - hz*d1y);
    float g1y = q * (c.z*a.x - c.x*a.z) - s * (hz*d1x - hx*d1z);
    float g1z = q * (c.x*a.y - c.y*a.x) - s * (hx*d1y - hy*d1x);
    float g2x = q * (a.y*b.z - a.z*b.y) - s * (hy*e1z - hz*e1y);
    float g2y = q * (a.z*b.x - a.x*b.z) - s * (hz*e1x - hx*e1z);
    float g2z = q * (a.x*b.y - a.y*b.x) - s * (hx*e1y - hy*e1x);

    red4(&xd[i0], g0x, g0y, g0z);
    red4(&xd[i1], g1x, g1y, g1z);
    red4(&xd[i2], g2x, g2y, g2z);
}

// Pass 2: forces with exact p, 2 faces/thread, scattered into x'.
__global__ void __launch_bounds__(256) k_force(int src) {
    int i = blockIdx.x * 256 + threadIdx.x;            // pair index
    if (i >= NFACES/2) return;
    const float4* __restrict__ xs = g_x[src];
    float4* xd = g_x[src ^ 1];

    ulonglong2 fp = __ldg((const ulonglong2*)g_fp + i);
    float q = g_p * (DT / 6.0f);     // dt * p * (cross/6)
    const float s = 0.5f * DT;       // dt * SURFACE_TENSION * 0.5

    face_force(xs, xd, fp.x, q, s);
    face_force(xs, xd, fp.y, q, s);
}

// Final: unpad into d_out.
__global__ void __launch_bounds__(256) k_pack(float* __restrict__ out, int src) {
    int i = blockIdx.x * 256 + threadIdx.x;
    if (i < NVERTS) {
        float4 v = g_x[src][i];
        out[3*i] = v.x; out[3*i+1] = v.y; out[3*i+2] = v.z;
    }
}

extern "C" void kernel_launch(void* const* d_in, const int* in_sizes, int n_in,
                              void* d_out, int out_size) {
    const float* verts;
    const void* faces;
    if (in_sizes[0] == 3 * NVERTS) { verts = (const float*)d_in[0]; faces = d_in[1]; }
    else                           { verts = (const float*)d_in[1]; faces = d_in[0]; }

    const int FB  = NFACES / 256;                   // 15625
    const int VB4 = (NFACES/4 + 255) / 256;         // 3907: 4 faces/thread, copy 2v/t
    const int FB2 = (NFACES/2 + 255) / 256;         // 7813: 2 faces/thread
    const int CB  = (NVERTS + 255) / 256;

    k_init<<<FB, 256>>>(verts, faces);
    int src = 0;
    for (int it = 0; it < NITERS; it++) {
        k_vol<<<VB4, 256>>>(src);                   // copy + exact p(x_t)
        k_force<<<FB2, 256>>>(src);                 // forces into x'
        src ^= 1;
    }
    k_pack<<<CB, 256>>>((float*)d_out, src);
}